// round 1
// baseline (speedup 1.0000x reference)
#include <cuda_runtime.h>
#include <math.h>

// Problem constants
constexpr int BATCH = 2;
constexpr int NPIX  = 65536;   // 256*256
constexpr int HI = 256, WI = 256;
constexpr int HL = 64,  WL = 64;
constexpr int CH = 128;

constexpr int D0 = 386, D1 = 1024, D2 = 512, D3 = 256, D4 = 128;

constexpr int MPIX  = 8;          // pixels per block
constexpr int MROWS = 32;         // 4 branches * MPIX rows
constexpr int NTHREADS = 256;

// smem: bufA holds X0T(386x32), X2T(512x32), X4T(128x32) -> 512*32 floats
//       bufB holds X1T(1024x32), X3T(256x32), l5 scratch -> 1024*32 floats
constexpr int BUFA_FLOATS = 512 * MROWS;    // 64 KB
constexpr int BUFB_FLOATS = 1024 * MROWS;   // 128 KB
constexpr int SMEM_BYTES = (BUFA_FLOATS + BUFB_FLOATS) * 4;  // 192 KB

#define DEVINL __device__ __forceinline__

// ---- packed f32x2 helpers (FFMA2 path; ptxas won't emit from C++) ----
DEVINL unsigned long long ffma2(unsigned long long a, unsigned long long b, unsigned long long c) {
    unsigned long long d;
    asm("fma.rn.f32x2 %0, %1, %2, %3;" : "=l"(d) : "l"(a), "l"(b), "l"(c));
    return d;
}
DEVINL unsigned long long pack2(float lo, float hi) {
    unsigned long long d;
    asm("mov.b64 %0, {%1, %2};" : "=l"(d) : "f"(lo), "f"(hi));
    return d;
}
DEVINL float2 unpack2(unsigned long long d) {
    float lo, hi;
    asm("mov.b64 {%0, %1}, %2;" : "=f"(lo), "=f"(hi) : "l"(d));
    return make_float2(lo, hi);
}

// One fully-connected layer: Xout[NOUT][32] = act(Xin[K][32]^T @ W[K][NOUT] + B)
// Activations stored TRANSPOSED in smem: X[k*32 + row].
// Thread layout: ty = tid>>5 owns rows ty*4..ty*4+3 (as two f32x2 row-pairs),
// tx = tid&31 owns 4 consecutive cols per group via float4 weight loads.
template<int K, int NOUT, bool RELU>
DEVINL void layer(const float* Xin, const float* __restrict__ Wg,
                  const float* __restrict__ Bg, float* Xout, int tx, int ty)
{
    constexpr int G = (NOUT >= 256) ? 2 : 1;   // float4 col-groups per thread
    constexpr int CPP = 128 * G;               // cols per pass
    constexpr int PASSES = NOUT / CPP;
    const int r0 = ty * 4;

    for (int pass = 0; pass < PASSES; ++pass) {
        const int c0 = pass * CPP + tx * 4;

        unsigned long long acc[2][4 * G];
        #pragma unroll
        for (int g = 0; g < G; ++g) {
            float4 b4 = *reinterpret_cast<const float4*>(Bg + c0 + 128 * g);
            float bb[4] = {b4.x, b4.y, b4.z, b4.w};
            #pragma unroll
            for (int j = 0; j < 4; ++j) {
                unsigned long long bp = pack2(bb[j], bb[j]);
                acc[0][4 * g + j] = bp;
                acc[1][4 * g + j] = bp;
            }
        }

        const float* wbase = Wg + c0;
        #pragma unroll 4
        for (int k = 0; k < K; ++k) {
            // row pairs come packed straight out of transposed smem (LDS.64)
            unsigned long long a01 = *reinterpret_cast<const unsigned long long*>(Xin + k * MROWS + r0);
            unsigned long long a23 = *reinterpret_cast<const unsigned long long*>(Xin + k * MROWS + r0 + 2);
            #pragma unroll
            for (int g = 0; g < G; ++g) {
                float4 w4 = *reinterpret_cast<const float4*>(wbase + (size_t)k * NOUT + 128 * g);
                float ww[4] = {w4.x, w4.y, w4.z, w4.w};
                #pragma unroll
                for (int j = 0; j < 4; ++j) {
                    unsigned long long w2 = pack2(ww[j], ww[j]);
                    acc[0][4 * g + j] = ffma2(a01, w2, acc[0][4 * g + j]);
                    acc[1][4 * g + j] = ffma2(a23, w2, acc[1][4 * g + j]);
                }
            }
        }

        #pragma unroll
        for (int g = 0; g < G; ++g) {
            #pragma unroll
            for (int j = 0; j < 4; ++j) {
                int c = c0 + 128 * g + j;
                float2 v01 = unpack2(acc[0][4 * g + j]);
                float2 v23 = unpack2(acc[1][4 * g + j]);
                float4 v = make_float4(v01.x, v01.y, v23.x, v23.y);
                if (RELU) {
                    v.x = fmaxf(v.x, 0.f); v.y = fmaxf(v.y, 0.f);
                    v.z = fmaxf(v.z, 0.f); v.w = fmaxf(v.w, 0.f);
                }
                *reinterpret_cast<float4*>(Xout + c * MROWS + r0) = v;
            }
        }
    }
}

__global__ __launch_bounds__(NTHREADS, 1)
void jiif_fused_kernel(
    const float* __restrict__ feat,      // [B,128,64,64]
    const float* __restrict__ coord,     // [B,N,2]
    const float* __restrict__ hr_guide,  // [B,128,256,256]
    const float* __restrict__ lr_guide,  // [B,128,64,64]
    const float* __restrict__ w1, const float* __restrict__ b1,
    const float* __restrict__ w2, const float* __restrict__ b2,
    const float* __restrict__ w3, const float* __restrict__ b3,
    const float* __restrict__ w4, const float* __restrict__ b4,
    const float* __restrict__ w5, const float* __restrict__ b5,
    float* __restrict__ out)             // [B,N,1]
{
    extern __shared__ float smem[];
    float* bufA = smem;                 // 512*32 floats
    float* bufB = smem + BUFA_FLOATS;   // 1024*32 floats

    const int tid  = threadIdx.x;
    const int lane = tid & 31;
    const int warp = tid >> 5;
    const int tx = lane, ty = warp;

    // ---------------- Gather stage: build X0T [386][32] into bufA ----------------
    // row = pi*4 + br; pi = local pixel 0..7, br = branch 0..3 (vx=-1,-1,1,1 / vy=-1,1,-1,1)
    for (int rr = 0; rr < 4; ++rr) {
        int row = warp * 4 + rr;
        int pi = row >> 2;
        int br = row & 3;

        int p = blockIdx.x * MPIX + pi;     // global pixel id (b*N + n)
        int b = p >> 16;
        // n = p & 65535 (not needed explicitly; indices come from coords)

        float y = coord[(size_t)p * 2 + 0];
        float x = coord[(size_t)p * 2 + 1];

        // hr nearest sample indices (align_corners=False, zeros padding)
        int ihy = (int)floorf((y + 1.0f) * (0.5f * HI));
        int ihx = (int)floorf((x + 1.0f) * (0.5f * WI));
        bool vh = (ihy >= 0) & (ihy < HI) & (ihx >= 0) & (ihx < WI);
        int ihyc = min(max(ihy, 0), HI - 1);
        int ihxc = min(max(ihx, 0), WI - 1);

        // branch-shifted lr coords
        float vx = (br & 2) ? 1.0f : -1.0f;
        float vy = (br & 1) ? 1.0f : -1.0f;
        float cy = y + vx * (1.0f / (float)HL);
        float cx = x + vy * (1.0f / (float)WL);
        int iy = (int)floorf((cy + 1.0f) * (0.5f * HL));
        int ix = (int)floorf((cx + 1.0f) * (0.5f * WL));
        bool v = (iy >= 0) & (iy < HL) & (ix >= 0) & (ix < WL);
        int iyc = min(max(iy, 0), HL - 1);
        int ixc = min(max(ix, 0), WL - 1);

        // q_coord is ZEROED when invalid (grid_sample zeros padding applies to it too)
        float qy = v ? (-1.0f + (2 * iyc + 1) * (1.0f / (float)HL)) : 0.0f;
        float qx = v ? (-1.0f + (2 * ixc + 1) * (1.0f / (float)WL)) : 0.0f;
        float rel_y = (y - qy) * (float)HL;
        float rel_x = (x - qx) * (float)WL;

        const float* featb = feat     + (size_t)b * CH * HL * WL;
        const float* hrb   = hr_guide + (size_t)b * CH * HI * WI;
        const float* lrb   = lr_guide + (size_t)b * CH * HL * WL;
        int fidx = iyc * WL + ixc;
        int hidx = ihyc * WI + ihxc;

        for (int c = lane; c < CH; c += 32) {
            float qf = v  ? featb[c * (HL * WL) + fidx] : 0.0f;
            float gh = vh ? hrb[c * (HI * WI) + hidx]   : 0.0f;
            float gl = v  ? lrb[c * (HL * WL) + fidx]   : 0.0f;
            bufA[(c)        * MROWS + row] = qf;       // q_feat
            bufA[(128 + c)  * MROWS + row] = gh;       // q_guide_hr
            bufA[(256 + c)  * MROWS + row] = gh - gl;  // q_guide_hr - q_guide_lr
        }
        if (lane == 0) {
            bufA[384 * MROWS + row] = rel_y;
            bufA[385 * MROWS + row] = rel_x;
        }
    }
    __syncthreads();

    // ---------------- MLP ----------------
    layer<D0, D1, true >(bufA, w1, b1, bufB, tx, ty);  __syncthreads();
    layer<D1, D2, true >(bufB, w2, b2, bufA, tx, ty);  __syncthreads();
    layer<D2, D3, true >(bufA, w3, b3, bufB, tx, ty);  __syncthreads();
    layer<D3, D4, true >(bufB, w4, b4, bufA, tx, ty);  __syncthreads();

    // ---------------- Layer 5 (128 -> 2), per-row dot products ----------------
    float* l5 = bufB;   // 64 floats scratch: l5[row*2 + c]
    if (tid < MROWS * 2) {
        int row = tid >> 1;
        int c   = tid & 1;
        float acc = b5[c];
        #pragma unroll 8
        for (int k = 0; k < D4; ++k)
            acc += bufA[k * MROWS + row] * w5[k * 2 + c];
        l5[row * 2 + c] = acc;
    }
    __syncthreads();

    // ---------------- softmax-weighted combine, one thread per pixel ----------------
    if (tid < MPIX) {
        int pi = tid;
        float v0[4], v1[4];
        #pragma unroll
        for (int br = 0; br < 4; ++br) {
            v0[br] = l5[(pi * 4 + br) * 2 + 0];
            v1[br] = l5[(pi * 4 + br) * 2 + 1];
        }
        float m = fmaxf(fmaxf(v1[0], v1[1]), fmaxf(v1[2], v1[3]));
        float num = 0.f, den = 0.f;
        #pragma unroll
        for (int br = 0; br < 4; ++br) {
            float e = expf(v1[br] - m);
            num += v0[br] * e;
            den += e;
        }
        out[(size_t)blockIdx.x * MPIX + pi] = num / den;
    }
}

extern "C" void kernel_launch(void* const* d_in, const int* in_sizes, int n_in,
                              void* d_out, int out_size) {
    const float* feat     = (const float*)d_in[0];
    const float* coord    = (const float*)d_in[1];
    const float* hr_guide = (const float*)d_in[2];
    const float* lr_guide = (const float*)d_in[3];
    const float* w1 = (const float*)d_in[4];
    const float* b1 = (const float*)d_in[5];
    const float* w2 = (const float*)d_in[6];
    const float* b2 = (const float*)d_in[7];
    const float* w3 = (const float*)d_in[8];
    const float* b3 = (const float*)d_in[9];
    const float* w4 = (const float*)d_in[10];
    const float* b4 = (const float*)d_in[11];
    const float* w5 = (const float*)d_in[12];
    const float* b5 = (const float*)d_in[13];
    float* out = (float*)d_out;

    cudaFuncSetAttribute(jiif_fused_kernel,
                         cudaFuncAttributeMaxDynamicSharedMemorySize, SMEM_BYTES);

    int nblocks = (BATCH * NPIX) / MPIX;   // 16384
    jiif_fused_kernel<<<nblocks, NTHREADS, SMEM_BYTES>>>(
        feat, coord, hr_guide, lr_guide,
        w1, b1, w2, b2, w3, b3, w4, b4, w5, b5, out);
}